// round 15
// baseline (speedup 1.0000x reference)
#include <cuda_runtime.h>
#include <cuda_bf16.h>
#include <cstdint>
#include <math.h>

#define N_NODES 50000
#define N_EDGES 800000
#define D0 1024
#define D1 512
#define D2 128
#define DOUT 14

// ---------------- scratch (device globals; no allocs allowed) ----------------
__device__ float    g_deg[N_NODES];
__device__ float    g_dis[N_NODES];
__device__ int      g_cnt[N_NODES];
__device__ int      g_rowptr[N_NODES + 1];
__device__ int      g_src[N_EDGES];
__device__ float    g_wgt[N_EDGES];
__device__ int      g_is64;
// Packed weights: [ntile][stage] x 3072 words (8 chunks x 32 lanes x 12-word slots,
// 8 real bf16x2 words + 4 pad). W1: 4 ntiles x 32 stages. W2: 1 x 16.
__device__ uint32_t g_w1p[4 * 32 * 3072];
__device__ uint32_t g_w2p[1 * 16 * 3072];
__device__ uint32_t g_h1b[(size_t)N_NODES * (D1 / 2)];   // X@W1, bf16
__device__ uint32_t g_a1b[(size_t)N_NODES * (D1 / 2)];   // relu(agg+b1), bf16
__device__ uint32_t g_h2b[(size_t)N_NODES * (D2 / 2)];   // a1@W2, bf16

// ---------------- small helpers ----------------
__device__ __forceinline__ uint32_t pack_bf2(float lo, float hi) {
    uint32_t w;
    asm("cvt.rn.bf16x2.f32 %0, %1, %2;" : "=r"(w) : "f"(hi), "f"(lo));
    return w;
}
__device__ __forceinline__ float2 bf2f(uint32_t w) {
    float2 r;
    r.x = __uint_as_float(w << 16);
    r.y = __uint_as_float(w & 0xffff0000u);
    return r;
}

// ---------------- edge-index dtype detection (int64 vs int32) ----------------
__global__ void detect_idx_kernel(const void* eidx) {
    int lane = threadIdx.x & 31;
    const int* p = (const int*)eidx;
    int bad = 0;
#pragma unroll
    for (int k = 0; k < 32; k++) bad |= p[2 * (k * 32 + lane) + 1];
    unsigned m = __ballot_sync(0xffffffffu, bad != 0);
    if (lane == 0) g_is64 = (m == 0) ? 1 : 0;
}

__device__ __forceinline__ int get_idx(const void* base, long i) {
    if (g_is64) return (int)((const long long*)base)[i];
    return ((const int*)base)[i];
}

// ---------------- conversions ----------------
// W fp32 [K][N] -> fragment-packed bf16 words (see R14 layout comment).
__global__ void conv_w_packed(const float* __restrict__ W, uint32_t* __restrict__ out,
                              int K, int N) {
    int i = blockIdx.x * blockDim.x + threadIdx.x;
    int Kw = K / 2;
    int stages = Kw / 16;
    int ntiles = N / 128;
    int total = ntiles * stages * 2048;
    if (i >= total) return;
    int ntile = i / (stages * 2048);
    int rem = i - ntile * (stages * 2048);
    int stg = rem >> 11;
    int r2 = rem & 2047;
    int c = r2 >> 8;             // 0..7
    int lane = (r2 >> 3) & 31;
    int j = r2 & 7;
    int s = c >> 2, wn2 = (c >> 1) & 1, h = c & 1;
    int nj = j >> 1, d = j & 1;
    int t = lane & 3, g = lane >> 2;
    int kw = stg * 16 + s * 8 + t + d * 4;
    int n = ntile * 128 + wn2 * 64 + (h * 4 + nj) * 8 + g;
    uint32_t w = pack_bf2(W[(2 * kw) * N + n], W[(2 * kw + 1) * N + n]);
    out[((size_t)(ntile * stages + stg)) * 3072 + (c * 32 + lane) * 12 + j] = w;
}

// ---------------- degree / normalization / CSR build ----------------
__global__ void init_kernel() {
    int i = blockIdx.x * blockDim.x + threadIdx.x;
    if (i < N_NODES) { g_deg[i] = 1.0f; g_cnt[i] = 0; }
}

__global__ void edge_deg_kernel(const void* eidx, const float* __restrict__ ew) {
    int e = blockIdx.x * blockDim.x + threadIdx.x;
    if (e < N_EDGES) {
        int c = get_idx(eidx, (long)N_EDGES + e);
        atomicAdd(&g_deg[c], ew[e]);
        atomicAdd(&g_cnt[c], 1);
    }
}

__global__ void dis_kernel() {
    int i = blockIdx.x * blockDim.x + threadIdx.x;
    if (i < N_NODES) g_dis[i] = rsqrtf(g_deg[i]);
}

__global__ void scan_kernel() {
    __shared__ int part[1024];
    int tid = threadIdx.x;
    const int chunk = (N_NODES + 1023) / 1024;
    int start = tid * chunk;
    int end = start + chunk; if (end > N_NODES) end = N_NODES;
    int s = 0;
    for (int i = start; i < end; i++) s += g_cnt[i];
    part[tid] = s;
    __syncthreads();
    if (tid == 0) {
        int run = 0;
        for (int i = 0; i < 1024; i++) { int v = part[i]; part[i] = run; run += v; }
        g_rowptr[N_NODES] = run;
    }
    __syncthreads();
    int run = part[tid];
    for (int i = start; i < end; i++) {
        g_rowptr[i] = run;
        run += g_cnt[i];
        g_cnt[i] = 0;
    }
}

__global__ void scatter_kernel(const void* eidx, const float* __restrict__ ew) {
    int e = blockIdx.x * blockDim.x + threadIdx.x;
    if (e < N_EDGES) {
        int r = get_idx(eidx, e);
        int c = get_idx(eidx, (long)N_EDGES + e);
        int pos = g_rowptr[c] + atomicAdd(&g_cnt[c], 1);
        g_src[pos] = r;
        g_wgt[pos] = ew[e] * g_dis[r];
    }
}

// ---------------- shared GEMM constants ----------------
#define BM 128
#define BN 128
#define BK 32
#define B_PKW 3072                       // packed B words per stage (incl. pad)

__device__ __forceinline__ void mma_bf16(float* d, const uint32_t* a, const uint32_t* b) {
    asm volatile(
        "mma.sync.aligned.m16n8k16.row.col.f32.bf16.bf16.f32 "
        "{%0,%1,%2,%3}, {%4,%5,%6,%7}, {%8,%9}, {%0,%1,%2,%3};"
        : "+f"(d[0]), "+f"(d[1]), "+f"(d[2]), "+f"(d[3])
        : "r"(a[0]), "r"(a[1]), "r"(a[2]), "r"(a[3]), "r"(b[0]), "r"(b[1]));
}

__device__ __forceinline__ void cp_async16(void* smem_ptr, const void* gptr, int srcsize) {
    unsigned int sa = (unsigned int)__cvta_generic_to_shared(smem_ptr);
    asm volatile("cp.async.cg.shared.global [%0], [%1], 16, %2;\n"
                 :: "r"(sa), "l"(gptr), "r"(srcsize));
}

// ============ GEMM1: A fp32 in gmem (conversion fused), B packed ============
#define AW1 40
#define A1_SZW (BM * AW1)
#define STG1_SZW (A1_SZW + B_PKW)       // 8192 words
#define STAGES1 3
#define GEMM1_SMEM_BYTES (STAGES1 * STG1_SZW * 4)   // 98304 B

__device__ __forceinline__ void load_stage_f32a(
    const float* __restrict__ Agm, const uint32_t* __restrict__ Bpk,
    int M, int K, int rowBase, int k0,
    float* As, uint32_t* Bs, int tid)
{
#pragma unroll
    for (int p = 0; p < 4; p++) {
        int idx = p * 256 + tid;
        int r = idx >> 3, c = idx & 7;
        int gr = rowBase + r;
        int sz = (gr < M) ? 16 : 0;
        int grc = (gr < M) ? gr : 0;
        cp_async16(&As[r * AW1 + c * 4], Agm + (size_t)grc * K + k0 + c * 4, sz);
    }
    const uint32_t* bsrc = Bpk + (size_t)(k0 / BK) * B_PKW;
#pragma unroll
    for (int p = 0; p < 3; p++) {
        int idx = p * 256 + tid;
        cp_async16(&Bs[idx * 4], bsrc + idx * 4, 16);
    }
}

__global__ __launch_bounds__(256, 2)
void f32a_gemm(const float* __restrict__ Agm, const uint32_t* __restrict__ Bpk_all,
               uint32_t* __restrict__ Cw, int M, int K, int N) {
    extern __shared__ uint32_t smem_dyn[];

    int tid = threadIdx.x;
    int warp = tid >> 5, lane = tid & 31;
    int g = lane >> 2, t = lane & 3;
    int wm = (warp >> 1) * 32;
    int wn2 = warp & 1;

    int rowBase = blockIdx.y * BM;
    int colBase = blockIdx.x * BN;
    int Nw = N / 2;
    int niter = K / BK;
    const uint32_t* Bpk = Bpk_all + (size_t)blockIdx.x * niter * B_PKW;

    float acc[2][8][4];
#pragma unroll
    for (int mi = 0; mi < 2; mi++)
#pragma unroll
        for (int ni = 0; ni < 8; ni++)
#pragma unroll
            for (int r = 0; r < 4; r++) acc[mi][ni][r] = 0.f;

#pragma unroll
    for (int p = 0; p < STAGES1 - 1; p++) {
        if (p < niter)
            load_stage_f32a(Agm, Bpk, M, K, rowBase, p * BK,
                            (float*)(smem_dyn + p * STG1_SZW),
                            smem_dyn + p * STG1_SZW + A1_SZW, tid);
        asm volatile("cp.async.commit_group;\n");
    }

    int s_cur = 0, s_load = STAGES1 - 1;

    for (int i = 0; i < niter; i++) {
        asm volatile("cp.async.wait_group 1;\n");
        __syncthreads();

        int inext = i + STAGES1 - 1;
        if (inext < niter)
            load_stage_f32a(Agm, Bpk, M, K, rowBase, inext * BK,
                            (float*)(smem_dyn + s_load * STG1_SZW),
                            smem_dyn + s_load * STG1_SZW + A1_SZW, tid);
        asm volatile("cp.async.commit_group;\n");

        const float* Asf = (const float*)(smem_dyn + s_cur * STG1_SZW);
        const uint32_t* Bs = smem_dyn + s_cur * STG1_SZW + A1_SZW;
#pragma unroll
        for (int s = 0; s < 2; s++) {
            uint32_t a[2][4];
#pragma unroll
            for (int mi = 0; mi < 2; mi++) {
                int r0 = (wm + mi * 16 + g) * AW1 + s * 16 + 2 * t;
                int r1 = (wm + mi * 16 + g + 8) * AW1 + s * 16 + 2 * t;
                float2 f;
                f = *(const float2*)&Asf[r0];     a[mi][0] = pack_bf2(f.x, f.y);
                f = *(const float2*)&Asf[r1];     a[mi][1] = pack_bf2(f.x, f.y);
                f = *(const float2*)&Asf[r0 + 8]; a[mi][2] = pack_bf2(f.x, f.y);
                f = *(const float2*)&Asf[r1 + 8]; a[mi][3] = pack_bf2(f.x, f.y);
            }
#pragma unroll
            for (int h = 0; h < 2; h++) {
                int c = s * 4 + wn2 * 2 + h;
                const uint32_t* bp = Bs + (c * 32 + lane) * 12;
                uint4 q0 = *(const uint4*)bp;
                uint4 q1 = *(const uint4*)(bp + 4);
                uint32_t b[4][2] = {{q0.x, q0.y}, {q0.z, q0.w},
                                    {q1.x, q1.y}, {q1.z, q1.w}};
#pragma unroll
                for (int mi = 0; mi < 2; mi++)
#pragma unroll
                    for (int nj = 0; nj < 4; nj++)
                        mma_bf16(acc[mi][h * 4 + nj], a[mi], b[nj]);
            }
        }

        s_cur  = (s_cur  + 1 == STAGES1) ? 0 : s_cur  + 1;
        s_load = (s_load + 1 == STAGES1) ? 0 : s_load + 1;
    }

#pragma unroll
    for (int mi = 0; mi < 2; mi++) {
        int row0 = rowBase + wm + mi * 16 + g;
        int row1 = row0 + 8;
#pragma unroll
        for (int ni = 0; ni < 8; ni++) {
            int cw = (colBase + wn2 * 64 + ni * 8) / 2 + t;
            if (row0 < M)
                Cw[(size_t)row0 * Nw + cw] = pack_bf2(acc[mi][ni][0], acc[mi][ni][1]);
            if (row1 < M)
                Cw[(size_t)row1 * Nw + cw] = pack_bf2(acc[mi][ni][2], acc[mi][ni][3]);
        }
    }
}

// ============ GEMM2: bf16 A, B packed ============
#define STAGES 4
#define AW 20
#define A_SZW (BM * AW)
#define STG_SZW (A_SZW + B_PKW)          // 5632 words
#define GEMM_SMEM_BYTES (STAGES * STG_SZW * 4)   // 90112 B

__device__ __forceinline__ void load_stage_bf(
    const uint32_t* __restrict__ Agm, const uint32_t* __restrict__ Bpk,
    int M, int Kw, int rowBase, int k0w,
    uint32_t* As, uint32_t* Bs, int tid)
{
#pragma unroll
    for (int p = 0; p < 2; p++) {
        int idx = p * 256 + tid;
        int r = idx >> 2, c = idx & 3;
        int gr = rowBase + r;
        int sz = (gr < M) ? 16 : 0;
        int grc = (gr < M) ? gr : 0;
        cp_async16(&As[r * AW + c * 4], Agm + (size_t)grc * Kw + k0w + c * 4, sz);
    }
    const uint32_t* bsrc = Bpk + (size_t)(k0w / 16) * B_PKW;
#pragma unroll
    for (int p = 0; p < 3; p++) {
        int idx = p * 256 + tid;
        cp_async16(&Bs[idx * 4], bsrc + idx * 4, 16);
    }
}

__global__ __launch_bounds__(256, 2)
void bf16gemm(const uint32_t* __restrict__ Agm, const uint32_t* __restrict__ Bpk_all,
              uint32_t* __restrict__ Cw, int M, int K, int N) {
    extern __shared__ uint32_t smem_dyn[];

    int tid = threadIdx.x;
    int warp = tid >> 5, lane = tid & 31;
    int g = lane >> 2, t = lane & 3;
    int wm = (warp >> 1) * 32;
    int wn2 = warp & 1;

    int rowBase = blockIdx.y * BM;
    int colBase = blockIdx.x * BN;
    int Kw = K / 2, Nw = N / 2;
    int niter = K / BK;
    const uint32_t* Bpk = Bpk_all + (size_t)blockIdx.x * niter * B_PKW;

    float acc[2][8][4];
#pragma unroll
    for (int mi = 0; mi < 2; mi++)
#pragma unroll
        for (int ni = 0; ni < 8; ni++)
#pragma unroll
            for (int r = 0; r < 4; r++) acc[mi][ni][r] = 0.f;

#pragma unroll
    for (int p = 0; p < STAGES - 1; p++) {
        if (p < niter)
            load_stage_bf(Agm, Bpk, M, Kw, rowBase, p * (BK / 2),
                          smem_dyn + p * STG_SZW, smem_dyn + p * STG_SZW + A_SZW, tid);
        asm volatile("cp.async.commit_group;\n");
    }

    int s_cur = 0, s_load = STAGES - 1;

    for (int i = 0; i < niter; i++) {
        asm volatile("cp.async.wait_group 2;\n");
        __syncthreads();

        int inext = i + STAGES - 1;
        if (inext < niter)
            load_stage_bf(Agm, Bpk, M, Kw, rowBase, inext * (BK / 2),
                          smem_dyn + s_load * STG_SZW,
                          smem_dyn + s_load * STG_SZW + A_SZW, tid);
        asm volatile("cp.async.commit_group;\n");

        const uint32_t* As = smem_dyn + s_cur * STG_SZW;
        const uint32_t* Bs = As + A_SZW;
#pragma unroll
        for (int s = 0; s < 2; s++) {
            uint32_t a[2][4];
#pragma unroll
            for (int mi = 0; mi < 2; mi++) {
                int row = wm + mi * 16;
                a[mi][0] = As[(row + g    ) * AW + s * 8 + t    ];
                a[mi][1] = As[(row + g + 8) * AW + s * 8 + t    ];
                a[mi][2] = As[(row + g    ) * AW + s * 8 + t + 4];
                a[mi][3] = As[(row + g + 8) * AW + s * 8 + t + 4];
            }
#pragma unroll
            for (int h = 0; h < 2; h++) {
                int c = s * 4 + wn2 * 2 + h;
                const uint32_t* bp = Bs + (c * 32 + lane) * 12;
                uint4 q0 = *(const uint4*)bp;
                uint4 q1 = *(const uint4*)(bp + 4);
                uint32_t b[4][2] = {{q0.x, q0.y}, {q0.z, q0.w},
                                    {q1.x, q1.y}, {q1.z, q1.w}};
#pragma unroll
                for (int mi = 0; mi < 2; mi++)
#pragma unroll
                    for (int nj = 0; nj < 4; nj++)
                        mma_bf16(acc[mi][h * 4 + nj], a[mi], b[nj]);
            }
        }

        s_cur  = (s_cur  + 1 == STAGES) ? 0 : s_cur  + 1;
        s_load = (s_load + 1 == STAGES) ? 0 : s_load + 1;
    }

#pragma unroll
    for (int mi = 0; mi < 2; mi++) {
        int row0 = rowBase + wm + mi * 16 + g;
        int row1 = row0 + 8;
#pragma unroll
        for (int ni = 0; ni < 8; ni++) {
            int cw = (colBase + wn2 * 64 + ni * 8) / 2 + t;
            if (row0 < M)
                Cw[(size_t)row0 * Nw + cw] = pack_bf2(acc[mi][ni][0], acc[mi][ni][1]);
            if (row1 < M)
                Cw[(size_t)row1 * Nw + cw] = pack_bf2(acc[mi][ni][2], acc[mi][ni][3]);
        }
    }
}

// ---------------- aggregation layer 1: 2 warps/node, 4-edge unroll ----------
// Each warp owns one uint4 (8 features) per lane: half of the 512-feat row.
__global__ __launch_bounds__(256)
void agg1_kernel(const float* __restrict__ b1) {
    int warp = threadIdx.x >> 5;
    int node = blockIdx.x * 4 + (warp >> 1);
    if (node >= N_NODES) return;
    int half = warp & 1;
    int lane = threadIdx.x & 31;
    int vi = half * 32 + lane;              // uint4 index within row, 0..63
    const uint4* h = (const uint4*)g_h1b;
    float dc = g_dis[node];

    float2 acc[4];
    {
        uint4 v = h[(size_t)node * 64 + vi];
        float2 f;
        f = bf2f(v.x); acc[0] = make_float2(f.x * dc, f.y * dc);
        f = bf2f(v.y); acc[1] = make_float2(f.x * dc, f.y * dc);
        f = bf2f(v.z); acc[2] = make_float2(f.x * dc, f.y * dc);
        f = bf2f(v.w); acc[3] = make_float2(f.x * dc, f.y * dc);
    }
    int beg = g_rowptr[node], end = g_rowptr[node + 1];
    int e = beg;
    for (; e + 3 < end; e += 4) {
        int r0 = g_src[e],     r1 = g_src[e + 1];
        int r2 = g_src[e + 2], r3 = g_src[e + 3];
        float w0 = g_wgt[e],     w1 = g_wgt[e + 1];
        float w2 = g_wgt[e + 2], w3 = g_wgt[e + 3];
        uint4 u0 = h[(size_t)r0 * 64 + vi];
        uint4 u1 = h[(size_t)r1 * 64 + vi];
        uint4 u2 = h[(size_t)r2 * 64 + vi];
        uint4 u3 = h[(size_t)r3 * 64 + vi];
        float2 f;
        f = bf2f(u0.x); acc[0].x += w0 * f.x; acc[0].y += w0 * f.y;
        f = bf2f(u0.y); acc[1].x += w0 * f.x; acc[1].y += w0 * f.y;
        f = bf2f(u0.z); acc[2].x += w0 * f.x; acc[2].y += w0 * f.y;
        f = bf2f(u0.w); acc[3].x += w0 * f.x; acc[3].y += w0 * f.y;
        f = bf2f(u1.x); acc[0].x += w1 * f.x; acc[0].y += w1 * f.y;
        f = bf2f(u1.y); acc[1].x += w1 * f.x; acc[1].y += w1 * f.y;
        f = bf2f(u1.z); acc[2].x += w1 * f.x; acc[2].y += w1 * f.y;
        f = bf2f(u1.w); acc[3].x += w1 * f.x; acc[3].y += w1 * f.y;
        f = bf2f(u2.x); acc[0].x += w2 * f.x; acc[0].y += w2 * f.y;
        f = bf2f(u2.y); acc[1].x += w2 * f.x; acc[1].y += w2 * f.y;
        f = bf2f(u2.z); acc[2].x += w2 * f.x; acc[2].y += w2 * f.y;
        f = bf2f(u2.w); acc[3].x += w2 * f.x; acc[3].y += w2 * f.y;
        f = bf2f(u3.x); acc[0].x += w3 * f.x; acc[0].y += w3 * f.y;
        f = bf2f(u3.y); acc[1].x += w3 * f.x; acc[1].y += w3 * f.y;
        f = bf2f(u3.z); acc[2].x += w3 * f.x; acc[2].y += w3 * f.y;
        f = bf2f(u3.w); acc[3].x += w3 * f.x; acc[3].y += w3 * f.y;
    }
    for (; e < end; e++) {
        int r = g_src[e];
        float w = g_wgt[e];
        uint4 u = h[(size_t)r * 64 + vi];
        float2 f;
        f = bf2f(u.x); acc[0].x += w * f.x; acc[0].y += w * f.y;
        f = bf2f(u.y); acc[1].x += w * f.x; acc[1].y += w * f.y;
        f = bf2f(u.z); acc[2].x += w * f.x; acc[2].y += w * f.y;
        f = bf2f(u.w); acc[3].x += w * f.x; acc[3].y += w * f.y;
    }
    const float2* bb = (const float2*)b1;   // 256 float2, index = word index
    uint32_t ow[4];
#pragma unroll
    for (int j = 0; j < 4; j++) {
        float2 bv = bb[4 * vi + j];
        float lo = fmaxf(dc * acc[j].x + bv.x, 0.f);
        float hi = fmaxf(dc * acc[j].y + bv.y, 0.f);
        ow[j] = pack_bf2(lo, hi);
    }
    ((uint4*)g_a1b)[(size_t)node * 64 + vi] = make_uint4(ow[0], ow[1], ow[2], ow[3]);
}

// ---------------- aggregation layer 2 (bf16 h2) fused with FC+sigmoid --------
__global__ __launch_bounds__(256)
void agg2_fc_kernel(const float* __restrict__ b2, const float* __restrict__ Wfc,
                    const float* __restrict__ bfc, float* __restrict__ out) {
    __shared__ float sh[8][128];
    __shared__ float sWfc[D2 * DOUT];
    for (int i = threadIdx.x; i < D2 * DOUT; i += blockDim.x) sWfc[i] = Wfc[i];
    __syncthreads();

    int wid = threadIdx.x >> 5;
    int lane = threadIdx.x & 31;
    int node = blockIdx.x * 8 + wid;

    if (node < N_NODES) {
        const uint2* h = (const uint2*)g_h2b;   // 32 uint2 per row
        float dc = g_dis[node];
        uint2 v = h[(size_t)node * 32 + lane];
        float2 f0 = bf2f(v.x), f1 = bf2f(v.y);
        float2 acc0 = make_float2(f0.x * dc, f0.y * dc);
        float2 acc1 = make_float2(f1.x * dc, f1.y * dc);
        int beg = g_rowptr[node], end = g_rowptr[node + 1];
        int e = beg;
        for (; e + 3 < end; e += 4) {
            int r0 = g_src[e],     r1 = g_src[e + 1];
            int r2 = g_src[e + 2], r3 = g_src[e + 3];
            float w0 = g_wgt[e],     w1 = g_wgt[e + 1];
            float w2 = g_wgt[e + 2], w3 = g_wgt[e + 3];
            uint2 u0 = h[(size_t)r0 * 32 + lane];
            uint2 u1 = h[(size_t)r1 * 32 + lane];
            uint2 u2 = h[(size_t)r2 * 32 + lane];
            uint2 u3 = h[(size_t)r3 * 32 + lane];
            float2 f;
            f = bf2f(u0.x); acc0.x += w0 * f.x; acc0.y += w0 * f.y;
            f = bf2f(u0.y); acc1.x += w0 * f.x; acc1.y += w0 * f.y;
            f = bf2f(u1.x); acc0.x += w1 * f.x; acc0.y += w1 * f.y;
            f = bf2f(u1.y); acc1.x += w1 * f.x; acc1.y += w1 * f.y;
            f = bf2f(u2.x); acc0.x += w2 * f.x; acc0.y += w2 * f.y;
            f = bf2f(u2.y); acc1.x += w2 * f.x; acc1.y += w2 * f.y;
            f = bf2f(u3.x); acc0.x += w3 * f.x; acc0.y += w3 * f.y;
            f = bf2f(u3.y); acc1.x += w3 * f.x; acc1.y += w3 * f.y;
        }
        for (; e < end; e++) {
            int r = g_src[e];
            float w = g_wgt[e];
            uint2 u = h[(size_t)r * 32 + lane];
            float2 g0 = bf2f(u.x), g1 = bf2f(u.y);
            acc0.x += w * g0.x; acc0.y += w * g0.y;
            acc1.x += w * g1.x; acc1.y += w * g1.y;
        }
        const float2* bb = (const float2*)b2;
        float2 b0 = bb[2 * lane], b1v = bb[2 * lane + 1];
        sh[wid][lane * 4 + 0] = fmaxf(dc * acc0.x + b0.x, 0.f);
        sh[wid][lane * 4 + 1] = fmaxf(dc * acc0.y + b0.y, 0.f);
        sh[wid][lane * 4 + 2] = fmaxf(dc * acc1.x + b1v.x, 0.f);
        sh[wid][lane * 4 + 3] = fmaxf(dc * acc1.y + b1v.y, 0.f);
    }
    __syncwarp();
    if (node < N_NODES && lane < DOUT) {
        float s = bfc[lane];
#pragma unroll 8
        for (int d = 0; d < D2; d++) s += sh[wid][d] * sWfc[d * DOUT + lane];
        out[(size_t)node * DOUT + lane] = 1.f / (1.f + expf(-s));
    }
}

// ---------------- launch ----------------
extern "C" void kernel_launch(void* const* d_in, const int* in_sizes, int n_in,
                              void* d_out, int out_size) {
    const float* x   = (const float*)d_in[0];
    const void*  eix = d_in[1];
    const float* ew  = (const float*)d_in[2];
    const float* W1  = (const float*)d_in[3];
    const float* b1  = (const float*)d_in[4];
    const float* W2  = (const float*)d_in[5];
    const float* b2  = (const float*)d_in[6];
    const float* Wfc = (const float*)d_in[7];
    const float* bfc = (const float*)d_in[8];
    float* out = (float*)d_out;

    uint32_t *w1p, *w2p, *h1b, *a1b, *h2b;
    cudaGetSymbolAddress((void**)&w1p, g_w1p);
    cudaGetSymbolAddress((void**)&w2p, g_w2p);
    cudaGetSymbolAddress((void**)&h1b, g_h1b);
    cudaGetSymbolAddress((void**)&a1b, g_a1b);
    cudaGetSymbolAddress((void**)&h2b, g_h2b);

    cudaFuncSetAttribute(f32a_gemm, cudaFuncAttributeMaxDynamicSharedMemorySize,
                         GEMM1_SMEM_BYTES);
    cudaFuncSetAttribute(bf16gemm, cudaFuncAttributeMaxDynamicSharedMemorySize,
                         GEMM_SMEM_BYTES);

    const int TB = 256;
    detect_idx_kernel<<<1, 32>>>(eix);                                        // 1
    conv_w_packed<<<(4 * 32 * 2048 + TB - 1) / TB, TB>>>(W1, w1p, D0, D1);    // 2
    init_kernel<<<(N_NODES + TB - 1) / TB, TB>>>();                           // 3

    dim3 g1(D1 / BN, (N_NODES + BM - 1) / BM);
    f32a_gemm<<<g1, 256, GEMM1_SMEM_BYTES>>>(x, w1p, h1b, N_NODES, D0, D1);   // 4 <- ncu

    edge_deg_kernel<<<(N_EDGES + TB - 1) / TB, TB>>>(eix, ew);                // 5
    dis_kernel<<<(N_NODES + TB - 1) / TB, TB>>>();                            // 6
    scan_kernel<<<1, 1024>>>();                                               // 7
    scatter_kernel<<<(N_EDGES + TB - 1) / TB, TB>>>(eix, ew);                 // 8

    agg1_kernel<<<(N_NODES + 3) / 4, 256>>>(b1);                              // 9

    conv_w_packed<<<(1 * 16 * 2048 + TB - 1) / TB, TB>>>(W2, w2p, D1, D2);    // 10

    dim3 g2(D2 / BN, (N_NODES + BM - 1) / BM);
    bf16gemm<<<g2, 256, GEMM_SMEM_BYTES>>>(a1b, w2p, h2b, N_NODES, D1, D2);   // 11

    agg2_fc_kernel<<<(N_NODES + 7) / 8, 256>>>(b2, Wfc, bfc, out);            // 12
}

// round 16
// speedup vs baseline: 1.1781x; 1.1781x over previous
#include <cuda_runtime.h>
#include <cuda_bf16.h>
#include <cstdint>
#include <math.h>

#define N_NODES 50000
#define N_EDGES 800000
#define D0 1024
#define D1 512
#define D2 128
#define DOUT 14

#define SCAN_TB 512
#define SCAN_NB ((N_NODES + SCAN_TB - 1) / SCAN_TB)   // 98

// ---------------- scratch (device globals; no allocs allowed) ----------------
__device__ float    g_deg[N_NODES];
__device__ float    g_dis[N_NODES];
__device__ int      g_cnt[N_NODES];
__device__ int      g_rowptr[N_NODES + 1];
__device__ int      g_part[SCAN_NB];
__device__ int2     g_edge[N_EDGES];     // (src, weight-bits) packed
__device__ int      g_is64;
// Packed weights: [ntile][stage] x 3072 words (8 chunks x 32 lanes x 12-word slots).
__device__ uint32_t g_w1p[4 * 32 * 3072];
__device__ uint32_t g_w2p[1 * 16 * 3072];
__device__ uint32_t g_h1b[(size_t)N_NODES * (D1 / 2)];   // X@W1, bf16
__device__ uint32_t g_a1b[(size_t)N_NODES * (D1 / 2)];   // relu(agg+b1), bf16
__device__ uint32_t g_h2b[(size_t)N_NODES * (D2 / 2)];   // a1@W2, bf16

// ---------------- small helpers ----------------
__device__ __forceinline__ uint32_t pack_bf2(float lo, float hi) {
    uint32_t w;
    asm("cvt.rn.bf16x2.f32 %0, %1, %2;" : "=r"(w) : "f"(hi), "f"(lo));
    return w;
}
__device__ __forceinline__ float2 bf2f(uint32_t w) {
    float2 r;
    r.x = __uint_as_float(w << 16);
    r.y = __uint_as_float(w & 0xffff0000u);
    return r;
}

// ---------------- edge-index dtype detection (int64 vs int32) ----------------
__global__ void detect_idx_kernel(const void* eidx) {
    int lane = threadIdx.x & 31;
    const int* p = (const int*)eidx;
    int bad = 0;
#pragma unroll
    for (int k = 0; k < 32; k++) bad |= p[2 * (k * 32 + lane) + 1];
    unsigned m = __ballot_sync(0xffffffffu, bad != 0);
    if (lane == 0) g_is64 = (m == 0) ? 1 : 0;
}

__device__ __forceinline__ int get_idx(const void* base, long i) {
    if (g_is64) return (int)((const long long*)base)[i];
    return ((const int*)base)[i];
}

// ---------------- conversions ----------------
// W fp32 [K][N] -> fragment-packed bf16 words (see R14 layout).
__global__ void conv_w_packed(const float* __restrict__ W, uint32_t* __restrict__ out,
                              int K, int N) {
    int i = blockIdx.x * blockDim.x + threadIdx.x;
    int Kw = K / 2;
    int stages = Kw / 16;
    int ntiles = N / 128;
    int total = ntiles * stages * 2048;
    if (i >= total) return;
    int ntile = i / (stages * 2048);
    int rem = i - ntile * (stages * 2048);
    int stg = rem >> 11;
    int r2 = rem & 2047;
    int c = r2 >> 8;
    int lane = (r2 >> 3) & 31;
    int j = r2 & 7;
    int s = c >> 2, wn2 = (c >> 1) & 1, h = c & 1;
    int nj = j >> 1, d = j & 1;
    int t = lane & 3, g = lane >> 2;
    int kw = stg * 16 + s * 8 + t + d * 4;
    int n = ntile * 128 + wn2 * 64 + (h * 4 + nj) * 8 + g;
    uint32_t w = pack_bf2(W[(2 * kw) * N + n], W[(2 * kw + 1) * N + n]);
    out[((size_t)(ntile * stages + stg)) * 3072 + (c * 32 + lane) * 12 + j] = w;
}

// ---------------- degree / normalization / CSR build ----------------
__global__ void init_kernel() {
    int i = blockIdx.x * blockDim.x + threadIdx.x;
    if (i < N_NODES) { g_deg[i] = 1.0f; g_cnt[i] = 0; }
}

__global__ void edge_deg_kernel(const void* eidx, const float* __restrict__ ew) {
    int e = blockIdx.x * blockDim.x + threadIdx.x;
    if (e < N_EDGES) {
        int c = get_idx(eidx, (long)N_EDGES + e);
        atomicAdd(&g_deg[c], ew[e]);
        atomicAdd(&g_cnt[c], 1);
    }
}

__global__ void dis_kernel() {
    int i = blockIdx.x * blockDim.x + threadIdx.x;
    if (i < N_NODES) g_dis[i] = rsqrtf(g_deg[i]);
}

// parallel scan: p1 block-reduce, p2 scan partials, p3 block-scan + write
__global__ void scan_p1() {
    __shared__ int sdata[SCAN_TB];
    int i = blockIdx.x * SCAN_TB + threadIdx.x;
    sdata[threadIdx.x] = (i < N_NODES) ? g_cnt[i] : 0;
    __syncthreads();
    for (int s = SCAN_TB / 2; s > 0; s >>= 1) {
        if (threadIdx.x < s) sdata[threadIdx.x] += sdata[threadIdx.x + s];
        __syncthreads();
    }
    if (threadIdx.x == 0) g_part[blockIdx.x] = sdata[0];
}

__global__ void scan_p2() {
    __shared__ int tmp[128];
    int t = threadIdx.x;
    tmp[t] = (t < SCAN_NB) ? g_part[t] : 0;
    __syncthreads();
    if (t == 0) {
        int run = 0;
        for (int i = 0; i < SCAN_NB; i++) { int v = tmp[i]; tmp[i] = run; run += v; }
        g_rowptr[N_NODES] = run;
    }
    __syncthreads();
    if (t < SCAN_NB) g_part[t] = tmp[t];
}

__global__ void scan_p3() {
    __shared__ int warpsum[16];
    int i = blockIdx.x * SCAN_TB + threadIdx.x;
    int lane = threadIdx.x & 31, wid = threadIdx.x >> 5;
    int v = (i < N_NODES) ? g_cnt[i] : 0;
    int x = v;
#pragma unroll
    for (int o = 1; o < 32; o <<= 1) {
        int y = __shfl_up_sync(0xffffffffu, x, o);
        if (lane >= o) x += y;
    }
    if (lane == 31) warpsum[wid] = x;
    __syncthreads();
    if (wid == 0 && lane < 16) {
        int s = warpsum[lane];
#pragma unroll
        for (int o = 1; o < 16; o <<= 1) {
            int y = __shfl_up_sync(0x0000ffffu, s, o);
            if (lane >= o) s += y;
        }
        warpsum[lane] = s;   // inclusive warp sums
    }
    __syncthreads();
    int base = g_part[blockIdx.x] + (wid > 0 ? warpsum[wid - 1] : 0);
    if (i < N_NODES) {
        g_rowptr[i] = base + x - v;   // exclusive
        g_cnt[i] = 0;
    }
}

__global__ void scatter_kernel(const void* eidx, const float* __restrict__ ew) {
    int e = blockIdx.x * blockDim.x + threadIdx.x;
    if (e < N_EDGES) {
        int r = get_idx(eidx, e);
        int c = get_idx(eidx, (long)N_EDGES + e);
        int pos = g_rowptr[c] + atomicAdd(&g_cnt[c], 1);
        g_edge[pos] = make_int2(r, __float_as_int(ew[e] * g_dis[r]));
    }
}

// ---------------- shared GEMM constants ----------------
#define BM 128
#define BN 128
#define BK 32
#define B_PKW 3072

__device__ __forceinline__ void mma_bf16(float* d, const uint32_t* a, const uint32_t* b) {
    asm volatile(
        "mma.sync.aligned.m16n8k16.row.col.f32.bf16.bf16.f32 "
        "{%0,%1,%2,%3}, {%4,%5,%6,%7}, {%8,%9}, {%0,%1,%2,%3};"
        : "+f"(d[0]), "+f"(d[1]), "+f"(d[2]), "+f"(d[3])
        : "r"(a[0]), "r"(a[1]), "r"(a[2]), "r"(a[3]), "r"(b[0]), "r"(b[1]));
}

__device__ __forceinline__ void cp_async16(void* smem_ptr, const void* gptr, int srcsize) {
    unsigned int sa = (unsigned int)__cvta_generic_to_shared(smem_ptr);
    asm volatile("cp.async.cg.shared.global [%0], [%1], 16, %2;\n"
                 :: "r"(sa), "l"(gptr), "r"(srcsize));
}

// ============ GEMM1: A fp32 in gmem (conversion fused), B packed ============
#define AW1 40
#define A1_SZW (BM * AW1)
#define STG1_SZW (A1_SZW + B_PKW)       // 8192 words
#define STAGES1 3
#define GEMM1_SMEM_BYTES (STAGES1 * STG1_SZW * 4)   // 98304 B

__device__ __forceinline__ void load_stage_f32a(
    const float* __restrict__ Agm, const uint32_t* __restrict__ Bpk,
    int M, int K, int rowBase, int k0,
    float* As, uint32_t* Bs, int tid)
{
#pragma unroll
    for (int p = 0; p < 4; p++) {
        int idx = p * 256 + tid;
        int r = idx >> 3, c = idx & 7;
        int gr = rowBase + r;
        int sz = (gr < M) ? 16 : 0;
        int grc = (gr < M) ? gr : 0;
        cp_async16(&As[r * AW1 + c * 4], Agm + (size_t)grc * K + k0 + c * 4, sz);
    }
    const uint32_t* bsrc = Bpk + (size_t)(k0 / BK) * B_PKW;
#pragma unroll
    for (int p = 0; p < 3; p++) {
        int idx = p * 256 + tid;
        cp_async16(&Bs[idx * 4], bsrc + idx * 4, 16);
    }
}

__global__ __launch_bounds__(256, 2)
void f32a_gemm(const float* __restrict__ Agm, const uint32_t* __restrict__ Bpk_all,
               uint32_t* __restrict__ Cw, int M, int K, int N) {
    extern __shared__ uint32_t smem_dyn[];

    int tid = threadIdx.x;
    int warp = tid >> 5, lane = tid & 31;
    int g = lane >> 2, t = lane & 3;
    int wm = (warp >> 1) * 32;
    int wn2 = warp & 1;

    int rowBase = blockIdx.y * BM;
    int colBase = blockIdx.x * BN;
    int Nw = N / 2;
    int niter = K / BK;
    const uint32_t* Bpk = Bpk_all + (size_t)blockIdx.x * niter * B_PKW;

    float acc[2][8][4];
#pragma unroll
    for (int mi = 0; mi < 2; mi++)
#pragma unroll
        for (int ni = 0; ni < 8; ni++)
#pragma unroll
            for (int r = 0; r < 4; r++) acc[mi][ni][r] = 0.f;

#pragma unroll
    for (int p = 0; p < STAGES1 - 1; p++) {
        if (p < niter)
            load_stage_f32a(Agm, Bpk, M, K, rowBase, p * BK,
                            (float*)(smem_dyn + p * STG1_SZW),
                            smem_dyn + p * STG1_SZW + A1_SZW, tid);
        asm volatile("cp.async.commit_group;\n");
    }

    int s_cur = 0, s_load = STAGES1 - 1;

    for (int i = 0; i < niter; i++) {
        asm volatile("cp.async.wait_group 1;\n");
        __syncthreads();

        int inext = i + STAGES1 - 1;
        if (inext < niter)
            load_stage_f32a(Agm, Bpk, M, K, rowBase, inext * BK,
                            (float*)(smem_dyn + s_load * STG1_SZW),
                            smem_dyn + s_load * STG1_SZW + A1_SZW, tid);
        asm volatile("cp.async.commit_group;\n");

        const float* Asf = (const float*)(smem_dyn + s_cur * STG1_SZW);
        const uint32_t* Bs = smem_dyn + s_cur * STG1_SZW + A1_SZW;
#pragma unroll
        for (int s = 0; s < 2; s++) {
            uint32_t a[2][4];
#pragma unroll
            for (int mi = 0; mi < 2; mi++) {
                int r0 = (wm + mi * 16 + g) * AW1 + s * 16 + 2 * t;
                int r1 = (wm + mi * 16 + g + 8) * AW1 + s * 16 + 2 * t;
                float2 f;
                f = *(const float2*)&Asf[r0];     a[mi][0] = pack_bf2(f.x, f.y);
                f = *(const float2*)&Asf[r1];     a[mi][1] = pack_bf2(f.x, f.y);
                f = *(const float2*)&Asf[r0 + 8]; a[mi][2] = pack_bf2(f.x, f.y);
                f = *(const float2*)&Asf[r1 + 8]; a[mi][3] = pack_bf2(f.x, f.y);
            }
#pragma unroll
            for (int h = 0; h < 2; h++) {
                int c = s * 4 + wn2 * 2 + h;
                const uint32_t* bp = Bs + (c * 32 + lane) * 12;
                uint4 q0 = *(const uint4*)bp;
                uint4 q1 = *(const uint4*)(bp + 4);
                uint32_t b[4][2] = {{q0.x, q0.y}, {q0.z, q0.w},
                                    {q1.x, q1.y}, {q1.z, q1.w}};
#pragma unroll
                for (int mi = 0; mi < 2; mi++)
#pragma unroll
                    for (int nj = 0; nj < 4; nj++)
                        mma_bf16(acc[mi][h * 4 + nj], a[mi], b[nj]);
            }
        }

        s_cur  = (s_cur  + 1 == STAGES1) ? 0 : s_cur  + 1;
        s_load = (s_load + 1 == STAGES1) ? 0 : s_load + 1;
    }

#pragma unroll
    for (int mi = 0; mi < 2; mi++) {
        int row0 = rowBase + wm + mi * 16 + g;
        int row1 = row0 + 8;
#pragma unroll
        for (int ni = 0; ni < 8; ni++) {
            int cw = (colBase + wn2 * 64 + ni * 8) / 2 + t;
            if (row0 < M)
                Cw[(size_t)row0 * Nw + cw] = pack_bf2(acc[mi][ni][0], acc[mi][ni][1]);
            if (row1 < M)
                Cw[(size_t)row1 * Nw + cw] = pack_bf2(acc[mi][ni][2], acc[mi][ni][3]);
        }
    }
}

// ============ GEMM2: bf16 A, B packed ============
#define STAGES 4
#define AW 20
#define A_SZW (BM * AW)
#define STG_SZW (A_SZW + B_PKW)          // 5632 words
#define GEMM_SMEM_BYTES (STAGES * STG_SZW * 4)   // 90112 B

__device__ __forceinline__ void load_stage_bf(
    const uint32_t* __restrict__ Agm, const uint32_t* __restrict__ Bpk,
    int M, int Kw, int rowBase, int k0w,
    uint32_t* As, uint32_t* Bs, int tid)
{
#pragma unroll
    for (int p = 0; p < 2; p++) {
        int idx = p * 256 + tid;
        int r = idx >> 2, c = idx & 3;
        int gr = rowBase + r;
        int sz = (gr < M) ? 16 : 0;
        int grc = (gr < M) ? gr : 0;
        cp_async16(&As[r * AW + c * 4], Agm + (size_t)grc * Kw + k0w + c * 4, sz);
    }
    const uint32_t* bsrc = Bpk + (size_t)(k0w / 16) * B_PKW;
#pragma unroll
    for (int p = 0; p < 3; p++) {
        int idx = p * 256 + tid;
        cp_async16(&Bs[idx * 4], bsrc + idx * 4, 16);
    }
}

__global__ __launch_bounds__(256, 2)
void bf16gemm(const uint32_t* __restrict__ Agm, const uint32_t* __restrict__ Bpk_all,
              uint32_t* __restrict__ Cw, int M, int K, int N) {
    extern __shared__ uint32_t smem_dyn[];

    int tid = threadIdx.x;
    int warp = tid >> 5, lane = tid & 31;
    int g = lane >> 2, t = lane & 3;
    int wm = (warp >> 1) * 32;
    int wn2 = warp & 1;

    int rowBase = blockIdx.y * BM;
    int colBase = blockIdx.x * BN;
    int Kw = K / 2, Nw = N / 2;
    int niter = K / BK;
    const uint32_t* Bpk = Bpk_all + (size_t)blockIdx.x * niter * B_PKW;

    float acc[2][8][4];
#pragma unroll
    for (int mi = 0; mi < 2; mi++)
#pragma unroll
        for (int ni = 0; ni < 8; ni++)
#pragma unroll
            for (int r = 0; r < 4; r++) acc[mi][ni][r] = 0.f;

#pragma unroll
    for (int p = 0; p < STAGES - 1; p++) {
        if (p < niter)
            load_stage_bf(Agm, Bpk, M, Kw, rowBase, p * (BK / 2),
                          smem_dyn + p * STG_SZW, smem_dyn + p * STG_SZW + A_SZW, tid);
        asm volatile("cp.async.commit_group;\n");
    }

    int s_cur = 0, s_load = STAGES - 1;

    for (int i = 0; i < niter; i++) {
        asm volatile("cp.async.wait_group 2;\n");
        __syncthreads();

        int inext = i + STAGES - 1;
        if (inext < niter)
            load_stage_bf(Agm, Bpk, M, Kw, rowBase, inext * (BK / 2),
                          smem_dyn + s_load * STG_SZW,
                          smem_dyn + s_load * STG_SZW + A_SZW, tid);
        asm volatile("cp.async.commit_group;\n");

        const uint32_t* As = smem_dyn + s_cur * STG_SZW;
        const uint32_t* Bs = As + A_SZW;
#pragma unroll
        for (int s = 0; s < 2; s++) {
            uint32_t a[2][4];
#pragma unroll
            for (int mi = 0; mi < 2; mi++) {
                int row = wm + mi * 16;
                a[mi][0] = As[(row + g    ) * AW + s * 8 + t    ];
                a[mi][1] = As[(row + g + 8) * AW + s * 8 + t    ];
                a[mi][2] = As[(row + g    ) * AW + s * 8 + t + 4];
                a[mi][3] = As[(row + g + 8) * AW + s * 8 + t + 4];
            }
#pragma unroll
            for (int h = 0; h < 2; h++) {
                int c = s * 4 + wn2 * 2 + h;
                const uint32_t* bp = Bs + (c * 32 + lane) * 12;
                uint4 q0 = *(const uint4*)bp;
                uint4 q1 = *(const uint4*)(bp + 4);
                uint32_t b[4][2] = {{q0.x, q0.y}, {q0.z, q0.w},
                                    {q1.x, q1.y}, {q1.z, q1.w}};
#pragma unroll
                for (int mi = 0; mi < 2; mi++)
#pragma unroll
                    for (int nj = 0; nj < 4; nj++)
                        mma_bf16(acc[mi][h * 4 + nj], a[mi], b[nj]);
            }
        }

        s_cur  = (s_cur  + 1 == STAGES) ? 0 : s_cur  + 1;
        s_load = (s_load + 1 == STAGES) ? 0 : s_load + 1;
    }

#pragma unroll
    for (int mi = 0; mi < 2; mi++) {
        int row0 = rowBase + wm + mi * 16 + g;
        int row1 = row0 + 8;
#pragma unroll
        for (int ni = 0; ni < 8; ni++) {
            int cw = (colBase + wn2 * 64 + ni * 8) / 2 + t;
            if (row0 < M)
                Cw[(size_t)row0 * Nw + cw] = pack_bf2(acc[mi][ni][0], acc[mi][ni][1]);
            if (row1 < M)
                Cw[(size_t)row1 * Nw + cw] = pack_bf2(acc[mi][ni][2], acc[mi][ni][3]);
        }
    }
}

// ---------------- aggregation layer 1 (R14 form, packed edges) ----------------
__global__ __launch_bounds__(256)
void agg1_kernel(const float* __restrict__ b1) {
    int node = blockIdx.x * 8 + (threadIdx.x >> 5);
    if (node >= N_NODES) return;
    int lane = threadIdx.x & 31;
    const uint4* h = (const uint4*)g_h1b;   // 64 uint4 per row
    float dc = g_dis[node];

    float2 acc[8];
    {
        uint4 v0 = h[(size_t)node * 64 + lane];
        uint4 v1 = h[(size_t)node * 64 + lane + 32];
        float2 f;
        f = bf2f(v0.x); acc[0] = make_float2(f.x * dc, f.y * dc);
        f = bf2f(v0.y); acc[1] = make_float2(f.x * dc, f.y * dc);
        f = bf2f(v0.z); acc[2] = make_float2(f.x * dc, f.y * dc);
        f = bf2f(v0.w); acc[3] = make_float2(f.x * dc, f.y * dc);
        f = bf2f(v1.x); acc[4] = make_float2(f.x * dc, f.y * dc);
        f = bf2f(v1.y); acc[5] = make_float2(f.x * dc, f.y * dc);
        f = bf2f(v1.z); acc[6] = make_float2(f.x * dc, f.y * dc);
        f = bf2f(v1.w); acc[7] = make_float2(f.x * dc, f.y * dc);
    }
    int beg = g_rowptr[node], end = g_rowptr[node + 1];
    if (beg < end) {
        int2 ed = g_edge[beg];
        for (int e = beg; e < end; e++) {
            int2 edn = make_int2(0, 0);
            if (e + 1 < end) edn = g_edge[e + 1];
            int r = ed.x;
            float w = __int_as_float(ed.y);
            uint4 u0 = h[(size_t)r * 64 + lane];
            uint4 u1 = h[(size_t)r * 64 + lane + 32];
            float2 f;
            f = bf2f(u0.x); acc[0].x += w * f.x; acc[0].y += w * f.y;
            f = bf2f(u0.y); acc[1].x += w * f.x; acc[1].y += w * f.y;
            f = bf2f(u0.z); acc[2].x += w * f.x; acc[2].y += w * f.y;
            f = bf2f(u0.w); acc[3].x += w * f.x; acc[3].y += w * f.y;
            f = bf2f(u1.x); acc[4].x += w * f.x; acc[4].y += w * f.y;
            f = bf2f(u1.y); acc[5].x += w * f.x; acc[5].y += w * f.y;
            f = bf2f(u1.z); acc[6].x += w * f.x; acc[6].y += w * f.y;
            f = bf2f(u1.w); acc[7].x += w * f.x; acc[7].y += w * f.y;
            ed = edn;
        }
    }
    const float2* bb = (const float2*)b1;   // 256 float2
    uint32_t ow[8];
#pragma unroll
    for (int j = 0; j < 8; j++) {
        int wordIdx = (j < 4) ? (4 * lane + j) : (128 + 4 * lane + (j - 4));
        float2 bv = bb[wordIdx];
        float lo = fmaxf(dc * acc[j].x + bv.x, 0.f);
        float hi = fmaxf(dc * acc[j].y + bv.y, 0.f);
        ow[j] = pack_bf2(lo, hi);
    }
    uint4* out = (uint4*)g_a1b;
    out[(size_t)node * 64 + lane]      = make_uint4(ow[0], ow[1], ow[2], ow[3]);
    out[(size_t)node * 64 + lane + 32] = make_uint4(ow[4], ow[5], ow[6], ow[7]);
}

// ---------------- aggregation layer 2 (bf16 h2) fused with FC+sigmoid --------
__global__ __launch_bounds__(256)
void agg2_fc_kernel(const float* __restrict__ b2, const float* __restrict__ Wfc,
                    const float* __restrict__ bfc, float* __restrict__ out) {
    __shared__ float sh[8][128];
    __shared__ float sWfc[D2 * DOUT];
    for (int i = threadIdx.x; i < D2 * DOUT; i += blockDim.x) sWfc[i] = Wfc[i];
    __syncthreads();

    int wid = threadIdx.x >> 5;
    int lane = threadIdx.x & 31;
    int node = blockIdx.x * 8 + wid;

    if (node < N_NODES) {
        const uint2* h = (const uint2*)g_h2b;   // 32 uint2 per row
        float dc = g_dis[node];
        uint2 v = h[(size_t)node * 32 + lane];
        float2 f0 = bf2f(v.x), f1 = bf2f(v.y);
        float2 acc0 = make_float2(f0.x * dc, f0.y * dc);
        float2 acc1 = make_float2(f1.x * dc, f1.y * dc);
        int beg = g_rowptr[node], end = g_rowptr[node + 1];
        for (int e = beg; e < end; e++) {
            int2 ed = g_edge[e];
            int r = ed.x;
            float w = __int_as_float(ed.y);
            uint2 u = h[(size_t)r * 32 + lane];
            float2 g0 = bf2f(u.x), g1 = bf2f(u.y);
            acc0.x += w * g0.x; acc0.y += w * g0.y;
            acc1.x += w * g1.x; acc1.y += w * g1.y;
        }
        const float2* bb = (const float2*)b2;
        float2 b0 = bb[2 * lane], b1v = bb[2 * lane + 1];
        sh[wid][lane * 4 + 0] = fmaxf(dc * acc0.x + b0.x, 0.f);
        sh[wid][lane * 4 + 1] = fmaxf(dc * acc0.y + b0.y, 0.f);
        sh[wid][lane * 4 + 2] = fmaxf(dc * acc1.x + b1v.x, 0.f);
        sh[wid][lane * 4 + 3] = fmaxf(dc * acc1.y + b1v.y, 0.f);
    }
    __syncwarp();
    if (node < N_NODES && lane < DOUT) {
        float s = bfc[lane];
#pragma unroll 8
        for (int d = 0; d < D2; d++) s += sh[wid][d] * sWfc[d * DOUT + lane];
        out[(size_t)node * DOUT + lane] = 1.f / (1.f + expf(-s));
    }
}

// ---------------- launch ----------------
extern "C" void kernel_launch(void* const* d_in, const int* in_sizes, int n_in,
                              void* d_out, int out_size) {
    const float* x   = (const float*)d_in[0];
    const void*  eix = d_in[1];
    const float* ew  = (const float*)d_in[2];
    const float* W1  = (const float*)d_in[3];
    const float* b1  = (const float*)d_in[4];
    const float* W2  = (const float*)d_in[5];
    const float* b2  = (const float*)d_in[6];
    const float* Wfc = (const float*)d_in[7];
    const float* bfc = (const float*)d_in[8];
    float* out = (float*)d_out;

    uint32_t *w1p, *w2p, *h1b, *a1b, *h2b;
    cudaGetSymbolAddress((void**)&w1p, g_w1p);
    cudaGetSymbolAddress((void**)&w2p, g_w2p);
    cudaGetSymbolAddress((void**)&h1b, g_h1b);
    cudaGetSymbolAddress((void**)&a1b, g_a1b);
    cudaGetSymbolAddress((void**)&h2b, g_h2b);

    cudaFuncSetAttribute(f32a_gemm, cudaFuncAttributeMaxDynamicSharedMemorySize,
                         GEMM1_SMEM_BYTES);
    cudaFuncSetAttribute(bf16gemm, cudaFuncAttributeMaxDynamicSharedMemorySize,
                         GEMM_SMEM_BYTES);

    const int TB = 256;
    detect_idx_kernel<<<1, 32>>>(eix);                                        // 1
    conv_w_packed<<<(4 * 32 * 2048 + TB - 1) / TB, TB>>>(W1, w1p, D0, D1);    // 2
    init_kernel<<<(N_NODES + TB - 1) / TB, TB>>>();                           // 3

    dim3 g1(D1 / BN, (N_NODES + BM - 1) / BM);
    f32a_gemm<<<g1, 256, GEMM1_SMEM_BYTES>>>(x, w1p, h1b, N_NODES, D0, D1);   // 4 <- ncu

    edge_deg_kernel<<<(N_EDGES + TB - 1) / TB, TB>>>(eix, ew);                // 5
    dis_kernel<<<(N_NODES + TB - 1) / TB, TB>>>();                            // 6
    scan_p1<<<SCAN_NB, SCAN_TB>>>();                                          // 7
    scan_p2<<<1, 128>>>();                                                    // 8
    scan_p3<<<SCAN_NB, SCAN_TB>>>();                                          // 9
    scatter_kernel<<<(N_EDGES + TB - 1) / TB, TB>>>(eix, ew);                 // 10

    agg1_kernel<<<(N_NODES + 7) / 8, 256>>>(b1);                              // 11

    conv_w_packed<<<(1 * 16 * 2048 + TB - 1) / TB, TB>>>(W2, w2p, D1, D2);    // 12

    dim3 g2(D2 / BN, (N_NODES + BM - 1) / BM);
    bf16gemm<<<g2, 256, GEMM_SMEM_BYTES>>>(a1b, w2p, h2b, N_NODES, D1, D2);   // 13

    agg2_fc_kernel<<<(N_NODES + 7) / 8, 256>>>(b2, Wfc, bfc, out);            // 14
}

// round 17
// speedup vs baseline: 1.2132x; 1.0298x over previous
#include <cuda_runtime.h>
#include <cuda_bf16.h>
#include <cstdint>
#include <math.h>

#define N_NODES 50000
#define N_EDGES 800000
#define D0 1024
#define D1 512
#define D2 128
#define DOUT 14

#define SCAN_TB 512
#define SCAN_NB ((N_NODES + SCAN_TB - 1) / SCAN_TB)   // 98

// ---------------- scratch (device globals; no allocs allowed) ----------------
__device__ unsigned long long g_degcnt[N_NODES];   // (cnt<<40) | fixpoint(sum ew, 2^-32)
__device__ float    g_dis[N_NODES];
__device__ int      g_cnt[N_NODES];
__device__ int      g_rowptr[N_NODES + 1];
__device__ int      g_part[SCAN_NB];
__device__ int2     g_edge[N_EDGES];     // (src, weight-bits) packed
__device__ int      g_is64;
// Packed weights: [ntile][stage] x 3072 words (8 chunks x 32 lanes x 12-word slots).
__device__ uint32_t g_w1p[4 * 32 * 3072];
__device__ uint32_t g_w2p[1 * 16 * 3072];
__device__ uint32_t g_h1b[(size_t)N_NODES * (D1 / 2)];   // X@W1, bf16
__device__ uint32_t g_a1b[(size_t)N_NODES * (D1 / 2)];   // relu(agg+b1), bf16
__device__ uint32_t g_h2b[(size_t)N_NODES * (D2 / 2)];   // a1@W2, bf16

// ---------------- small helpers ----------------
__device__ __forceinline__ uint32_t pack_bf2(float lo, float hi) {
    uint32_t w;
    asm("cvt.rn.bf16x2.f32 %0, %1, %2;" : "=r"(w) : "f"(hi), "f"(lo));
    return w;
}
__device__ __forceinline__ float2 bf2f(uint32_t w) {
    float2 r;
    r.x = __uint_as_float(w << 16);
    r.y = __uint_as_float(w & 0xffff0000u);
    return r;
}

// ---------------- detect (int64 vs int32) + init fused ----------------
__global__ void detect_init_kernel(const void* eidx) {
    int i = blockIdx.x * blockDim.x + threadIdx.x;
    if (i < N_NODES) g_degcnt[i] = 0ull;
    if (blockIdx.x == 0 && threadIdx.x < 32) {
        int lane = threadIdx.x;
        const int* p = (const int*)eidx;
        int bad = 0;
#pragma unroll
        for (int k = 0; k < 32; k++) bad |= p[2 * (k * 32 + lane) + 1];
        unsigned m = __ballot_sync(0xffffffffu, bad != 0);
        if (lane == 0) g_is64 = (m == 0) ? 1 : 0;
    }
}

__device__ __forceinline__ int get_idx(const void* base, long i) {
    if (g_is64) return (int)((const long long*)base)[i];
    return ((const int*)base)[i];
}

// ---------------- conversions ----------------
// W fp32 [K][N] -> fragment-packed bf16 words (see R14 layout).
__device__ __forceinline__ void conv_w_one(const float* __restrict__ W,
                                           uint32_t* __restrict__ out,
                                           int K, int N, int i) {
    int Kw = K / 2;
    int stages = Kw / 16;
    int rem_nt = i / (stages * 2048);
    int rem = i - rem_nt * (stages * 2048);
    int stg = rem >> 11;
    int r2 = rem & 2047;
    int c = r2 >> 8;
    int lane = (r2 >> 3) & 31;
    int j = r2 & 7;
    int s = c >> 2, wn2 = (c >> 1) & 1, h = c & 1;
    int nj = j >> 1, d = j & 1;
    int t = lane & 3, g = lane >> 2;
    int kw = stg * 16 + s * 8 + t + d * 4;
    int n = rem_nt * 128 + wn2 * 64 + (h * 4 + nj) * 8 + g;
    uint32_t w = pack_bf2(W[(2 * kw) * N + n], W[(2 * kw + 1) * N + n]);
    out[((size_t)(rem_nt * stages + stg)) * 3072 + (c * 32 + lane) * 12 + j] = w;
}

#define W1_TOTAL (4 * 32 * 2048)
#define W2_TOTAL (1 * 16 * 2048)

__global__ void conv_w_both(const float* __restrict__ W1, const float* __restrict__ W2,
                            uint32_t* __restrict__ o1, uint32_t* __restrict__ o2) {
    int i = blockIdx.x * blockDim.x + threadIdx.x;
    if (i < W1_TOTAL) conv_w_one(W1, o1, D0, D1, i);
    else if (i < W1_TOTAL + W2_TOTAL) conv_w_one(W2, o2, D1, D2, i - W1_TOTAL);
}

// ---------------- degree / CSR build ----------------
// Single packed atomic: (1<<40) per edge + ew in 2^-32 fixed point (40 bits).
__global__ void edge_deg_kernel(const void* eidx, const float* __restrict__ ew) {
    int e = blockIdx.x * blockDim.x + threadIdx.x;
    if (e < N_EDGES) {
        int c = get_idx(eidx, (long)N_EDGES + e);
        unsigned long long v = (1ull << 40) +
            (unsigned long long)(ew[e] * 4294967296.0f);
        atomicAdd(&g_degcnt[c], v);
    }
}

// scan p1 fused with decode + dis
__global__ void scan_p1() {
    __shared__ int sdata[SCAN_TB];
    int i = blockIdx.x * SCAN_TB + threadIdx.x;
    int c = 0;
    if (i < N_NODES) {
        unsigned long long v = g_degcnt[i];
        c = (int)(v >> 40);
        float deg = 1.0f + (float)(v & 0xFFFFFFFFFFull) * (1.0f / 4294967296.0f);
        g_dis[i] = rsqrtf(deg);
        g_cnt[i] = c;
    }
    sdata[threadIdx.x] = c;
    __syncthreads();
    for (int s = SCAN_TB / 2; s > 0; s >>= 1) {
        if (threadIdx.x < s) sdata[threadIdx.x] += sdata[threadIdx.x + s];
        __syncthreads();
    }
    if (threadIdx.x == 0) g_part[blockIdx.x] = sdata[0];
}

__global__ void scan_p2() {
    __shared__ int tmp[128];
    int t = threadIdx.x;
    tmp[t] = (t < SCAN_NB) ? g_part[t] : 0;
    __syncthreads();
    if (t == 0) {
        int run = 0;
        for (int i = 0; i < SCAN_NB; i++) { int v = tmp[i]; tmp[i] = run; run += v; }
        g_rowptr[N_NODES] = run;
    }
    __syncthreads();
    if (t < SCAN_NB) g_part[t] = tmp[t];
}

__global__ void scan_p3() {
    __shared__ int warpsum[16];
    int i = blockIdx.x * SCAN_TB + threadIdx.x;
    int lane = threadIdx.x & 31, wid = threadIdx.x >> 5;
    int v = (i < N_NODES) ? g_cnt[i] : 0;
    int x = v;
#pragma unroll
    for (int o = 1; o < 32; o <<= 1) {
        int y = __shfl_up_sync(0xffffffffu, x, o);
        if (lane >= o) x += y;
    }
    if (lane == 31) warpsum[wid] = x;
    __syncthreads();
    if (wid == 0 && lane < 16) {
        int s = warpsum[lane];
#pragma unroll
        for (int o = 1; o < 16; o <<= 1) {
            int y = __shfl_up_sync(0x0000ffffu, s, o);
            if (lane >= o) s += y;
        }
        warpsum[lane] = s;
    }
    __syncthreads();
    int base = g_part[blockIdx.x] + (wid > 0 ? warpsum[wid - 1] : 0);
    if (i < N_NODES) {
        g_rowptr[i] = base + x - v;
        g_cnt[i] = 0;
    }
}

__global__ void scatter_kernel(const void* eidx, const float* __restrict__ ew) {
    int e = blockIdx.x * blockDim.x + threadIdx.x;
    if (e < N_EDGES) {
        int r = get_idx(eidx, e);
        int c = get_idx(eidx, (long)N_EDGES + e);
        int pos = g_rowptr[c] + atomicAdd(&g_cnt[c], 1);
        g_edge[pos] = make_int2(r, __float_as_int(ew[e] * g_dis[r]));
    }
}

// ---------------- shared GEMM constants ----------------
#define BM 128
#define BN 128
#define BK 32
#define B_PKW 3072

__device__ __forceinline__ void mma_bf16(float* d, const uint32_t* a, const uint32_t* b) {
    asm volatile(
        "mma.sync.aligned.m16n8k16.row.col.f32.bf16.bf16.f32 "
        "{%0,%1,%2,%3}, {%4,%5,%6,%7}, {%8,%9}, {%0,%1,%2,%3};"
        : "+f"(d[0]), "+f"(d[1]), "+f"(d[2]), "+f"(d[3])
        : "r"(a[0]), "r"(a[1]), "r"(a[2]), "r"(a[3]), "r"(b[0]), "r"(b[1]));
}

__device__ __forceinline__ void cp_async16(void* smem_ptr, const void* gptr, int srcsize) {
    unsigned int sa = (unsigned int)__cvta_generic_to_shared(smem_ptr);
    asm volatile("cp.async.cg.shared.global [%0], [%1], 16, %2;\n"
                 :: "r"(sa), "l"(gptr), "r"(srcsize));
}

// ============ GEMM1: A fp32 in gmem (conversion fused), B packed ============
#define AW1 40
#define A1_SZW (BM * AW1)
#define STG1_SZW (A1_SZW + B_PKW)       // 8192 words
#define STAGES1 3
#define GEMM1_SMEM_BYTES (STAGES1 * STG1_SZW * 4)   // 98304 B

__device__ __forceinline__ void load_stage_f32a(
    const float* __restrict__ Agm, const uint32_t* __restrict__ Bpk,
    int M, int K, int rowBase, int k0,
    float* As, uint32_t* Bs, int tid)
{
#pragma unroll
    for (int p = 0; p < 4; p++) {
        int idx = p * 256 + tid;
        int r = idx >> 3, c = idx & 7;
        int gr = rowBase + r;
        int sz = (gr < M) ? 16 : 0;
        int grc = (gr < M) ? gr : 0;
        cp_async16(&As[r * AW1 + c * 4], Agm + (size_t)grc * K + k0 + c * 4, sz);
    }
    const uint32_t* bsrc = Bpk + (size_t)(k0 / BK) * B_PKW;
#pragma unroll
    for (int p = 0; p < 3; p++) {
        int idx = p * 256 + tid;
        cp_async16(&Bs[idx * 4], bsrc + idx * 4, 16);
    }
}

__global__ __launch_bounds__(256, 2)
void f32a_gemm(const float* __restrict__ Agm, const uint32_t* __restrict__ Bpk_all,
               uint32_t* __restrict__ Cw, int M, int K, int N) {
    extern __shared__ uint32_t smem_dyn[];

    int tid = threadIdx.x;
    int warp = tid >> 5, lane = tid & 31;
    int g = lane >> 2, t = lane & 3;
    int wm = (warp >> 1) * 32;
    int wn2 = warp & 1;

    int rowBase = blockIdx.y * BM;
    int colBase = blockIdx.x * BN;
    int Nw = N / 2;
    int niter = K / BK;
    const uint32_t* Bpk = Bpk_all + (size_t)blockIdx.x * niter * B_PKW;

    float acc[2][8][4];
#pragma unroll
    for (int mi = 0; mi < 2; mi++)
#pragma unroll
        for (int ni = 0; ni < 8; ni++)
#pragma unroll
            for (int r = 0; r < 4; r++) acc[mi][ni][r] = 0.f;

#pragma unroll
    for (int p = 0; p < STAGES1 - 1; p++) {
        if (p < niter)
            load_stage_f32a(Agm, Bpk, M, K, rowBase, p * BK,
                            (float*)(smem_dyn + p * STG1_SZW),
                            smem_dyn + p * STG1_SZW + A1_SZW, tid);
        asm volatile("cp.async.commit_group;\n");
    }

    int s_cur = 0, s_load = STAGES1 - 1;

    for (int i = 0; i < niter; i++) {
        asm volatile("cp.async.wait_group 1;\n");
        __syncthreads();

        int inext = i + STAGES1 - 1;
        if (inext < niter)
            load_stage_f32a(Agm, Bpk, M, K, rowBase, inext * BK,
                            (float*)(smem_dyn + s_load * STG1_SZW),
                            smem_dyn + s_load * STG1_SZW + A1_SZW, tid);
        asm volatile("cp.async.commit_group;\n");

        const float* Asf = (const float*)(smem_dyn + s_cur * STG1_SZW);
        const uint32_t* Bs = smem_dyn + s_cur * STG1_SZW + A1_SZW;
#pragma unroll
        for (int s = 0; s < 2; s++) {
            uint32_t a[2][4];
#pragma unroll
            for (int mi = 0; mi < 2; mi++) {
                int r0 = (wm + mi * 16 + g) * AW1 + s * 16 + 2 * t;
                int r1 = (wm + mi * 16 + g + 8) * AW1 + s * 16 + 2 * t;
                float2 f;
                f = *(const float2*)&Asf[r0];     a[mi][0] = pack_bf2(f.x, f.y);
                f = *(const float2*)&Asf[r1];     a[mi][1] = pack_bf2(f.x, f.y);
                f = *(const float2*)&Asf[r0 + 8]; a[mi][2] = pack_bf2(f.x, f.y);
                f = *(const float2*)&Asf[r1 + 8]; a[mi][3] = pack_bf2(f.x, f.y);
            }
#pragma unroll
            for (int h = 0; h < 2; h++) {
                int c = s * 4 + wn2 * 2 + h;
                const uint32_t* bp = Bs + (c * 32 + lane) * 12;
                uint4 q0 = *(const uint4*)bp;
                uint4 q1 = *(const uint4*)(bp + 4);
                uint32_t b[4][2] = {{q0.x, q0.y}, {q0.z, q0.w},
                                    {q1.x, q1.y}, {q1.z, q1.w}};
#pragma unroll
                for (int mi = 0; mi < 2; mi++)
#pragma unroll
                    for (int nj = 0; nj < 4; nj++)
                        mma_bf16(acc[mi][h * 4 + nj], a[mi], b[nj]);
            }
        }

        s_cur  = (s_cur  + 1 == STAGES1) ? 0 : s_cur  + 1;
        s_load = (s_load + 1 == STAGES1) ? 0 : s_load + 1;
    }

#pragma unroll
    for (int mi = 0; mi < 2; mi++) {
        int row0 = rowBase + wm + mi * 16 + g;
        int row1 = row0 + 8;
#pragma unroll
        for (int ni = 0; ni < 8; ni++) {
            int cw = (colBase + wn2 * 64 + ni * 8) / 2 + t;
            if (row0 < M)
                Cw[(size_t)row0 * Nw + cw] = pack_bf2(acc[mi][ni][0], acc[mi][ni][1]);
            if (row1 < M)
                Cw[(size_t)row1 * Nw + cw] = pack_bf2(acc[mi][ni][2], acc[mi][ni][3]);
        }
    }
}

// ============ GEMM2: bf16 A, B packed ============
#define STAGES 4
#define AW 20
#define A_SZW (BM * AW)
#define STG_SZW (A_SZW + B_PKW)          // 5632 words
#define GEMM_SMEM_BYTES (STAGES * STG_SZW * 4)   // 90112 B

__device__ __forceinline__ void load_stage_bf(
    const uint32_t* __restrict__ Agm, const uint32_t* __restrict__ Bpk,
    int M, int Kw, int rowBase, int k0w,
    uint32_t* As, uint32_t* Bs, int tid)
{
#pragma unroll
    for (int p = 0; p < 2; p++) {
        int idx = p * 256 + tid;
        int r = idx >> 2, c = idx & 3;
        int gr = rowBase + r;
        int sz = (gr < M) ? 16 : 0;
        int grc = (gr < M) ? gr : 0;
        cp_async16(&As[r * AW + c * 4], Agm + (size_t)grc * Kw + k0w + c * 4, sz);
    }
    const uint32_t* bsrc = Bpk + (size_t)(k0w / 16) * B_PKW;
#pragma unroll
    for (int p = 0; p < 3; p++) {
        int idx = p * 256 + tid;
        cp_async16(&Bs[idx * 4], bsrc + idx * 4, 16);
    }
}

__global__ __launch_bounds__(256, 2)
void bf16gemm(const uint32_t* __restrict__ Agm, const uint32_t* __restrict__ Bpk_all,
              uint32_t* __restrict__ Cw, int M, int K, int N) {
    extern __shared__ uint32_t smem_dyn[];

    int tid = threadIdx.x;
    int warp = tid >> 5, lane = tid & 31;
    int g = lane >> 2, t = lane & 3;
    int wm = (warp >> 1) * 32;
    int wn2 = warp & 1;

    int rowBase = blockIdx.y * BM;
    int colBase = blockIdx.x * BN;
    int Kw = K / 2, Nw = N / 2;
    int niter = K / BK;
    const uint32_t* Bpk = Bpk_all + (size_t)blockIdx.x * niter * B_PKW;

    float acc[2][8][4];
#pragma unroll
    for (int mi = 0; mi < 2; mi++)
#pragma unroll
        for (int ni = 0; ni < 8; ni++)
#pragma unroll
            for (int r = 0; r < 4; r++) acc[mi][ni][r] = 0.f;

#pragma unroll
    for (int p = 0; p < STAGES - 1; p++) {
        if (p < niter)
            load_stage_bf(Agm, Bpk, M, Kw, rowBase, p * (BK / 2),
                          smem_dyn + p * STG_SZW, smem_dyn + p * STG_SZW + A_SZW, tid);
        asm volatile("cp.async.commit_group;\n");
    }

    int s_cur = 0, s_load = STAGES - 1;

    for (int i = 0; i < niter; i++) {
        asm volatile("cp.async.wait_group 2;\n");
        __syncthreads();

        int inext = i + STAGES - 1;
        if (inext < niter)
            load_stage_bf(Agm, Bpk, M, Kw, rowBase, inext * (BK / 2),
                          smem_dyn + s_load * STG_SZW,
                          smem_dyn + s_load * STG_SZW + A_SZW, tid);
        asm volatile("cp.async.commit_group;\n");

        const uint32_t* As = smem_dyn + s_cur * STG_SZW;
        const uint32_t* Bs = As + A_SZW;
#pragma unroll
        for (int s = 0; s < 2; s++) {
            uint32_t a[2][4];
#pragma unroll
            for (int mi = 0; mi < 2; mi++) {
                int row = wm + mi * 16;
                a[mi][0] = As[(row + g    ) * AW + s * 8 + t    ];
                a[mi][1] = As[(row + g + 8) * AW + s * 8 + t    ];
                a[mi][2] = As[(row + g    ) * AW + s * 8 + t + 4];
                a[mi][3] = As[(row + g + 8) * AW + s * 8 + t + 4];
            }
#pragma unroll
            for (int h = 0; h < 2; h++) {
                int c = s * 4 + wn2 * 2 + h;
                const uint32_t* bp = Bs + (c * 32 + lane) * 12;
                uint4 q0 = *(const uint4*)bp;
                uint4 q1 = *(const uint4*)(bp + 4);
                uint32_t b[4][2] = {{q0.x, q0.y}, {q0.z, q0.w},
                                    {q1.x, q1.y}, {q1.z, q1.w}};
#pragma unroll
                for (int mi = 0; mi < 2; mi++)
#pragma unroll
                    for (int nj = 0; nj < 4; nj++)
                        mma_bf16(acc[mi][h * 4 + nj], a[mi], b[nj]);
            }
        }

        s_cur  = (s_cur  + 1 == STAGES) ? 0 : s_cur  + 1;
        s_load = (s_load + 1 == STAGES) ? 0 : s_load + 1;
    }

#pragma unroll
    for (int mi = 0; mi < 2; mi++) {
        int row0 = rowBase + wm + mi * 16 + g;
        int row1 = row0 + 8;
#pragma unroll
        for (int ni = 0; ni < 8; ni++) {
            int cw = (colBase + wn2 * 64 + ni * 8) / 2 + t;
            if (row0 < M)
                Cw[(size_t)row0 * Nw + cw] = pack_bf2(acc[mi][ni][0], acc[mi][ni][1]);
            if (row1 < M)
                Cw[(size_t)row1 * Nw + cw] = pack_bf2(acc[mi][ni][2], acc[mi][ni][3]);
        }
    }
}

// ---------------- aggregation layer 1 (packed edges) ----------------
__global__ __launch_bounds__(256)
void agg1_kernel(const float* __restrict__ b1) {
    int node = blockIdx.x * 8 + (threadIdx.x >> 5);
    if (node >= N_NODES) return;
    int lane = threadIdx.x & 31;
    const uint4* h = (const uint4*)g_h1b;   // 64 uint4 per row
    float dc = g_dis[node];

    float2 acc[8];
    {
        uint4 v0 = h[(size_t)node * 64 + lane];
        uint4 v1 = h[(size_t)node * 64 + lane + 32];
        float2 f;
        f = bf2f(v0.x); acc[0] = make_float2(f.x * dc, f.y * dc);
        f = bf2f(v0.y); acc[1] = make_float2(f.x * dc, f.y * dc);
        f = bf2f(v0.z); acc[2] = make_float2(f.x * dc, f.y * dc);
        f = bf2f(v0.w); acc[3] = make_float2(f.x * dc, f.y * dc);
        f = bf2f(v1.x); acc[4] = make_float2(f.x * dc, f.y * dc);
        f = bf2f(v1.y); acc[5] = make_float2(f.x * dc, f.y * dc);
        f = bf2f(v1.z); acc[6] = make_float2(f.x * dc, f.y * dc);
        f = bf2f(v1.w); acc[7] = make_float2(f.x * dc, f.y * dc);
    }
    int beg = g_rowptr[node], end = g_rowptr[node + 1];
    if (beg < end) {
        int2 ed = g_edge[beg];
        for (int e = beg; e < end; e++) {
            int2 edn = make_int2(0, 0);
            if (e + 1 < end) edn = g_edge[e + 1];
            int r = ed.x;
            float w = __int_as_float(ed.y);
            uint4 u0 = h[(size_t)r * 64 + lane];
            uint4 u1 = h[(size_t)r * 64 + lane + 32];
            float2 f;
            f = bf2f(u0.x); acc[0].x += w * f.x; acc[0].y += w * f.y;
            f = bf2f(u0.y); acc[1].x += w * f.x; acc[1].y += w * f.y;
            f = bf2f(u0.z); acc[2].x += w * f.x; acc[2].y += w * f.y;
            f = bf2f(u0.w); acc[3].x += w * f.x; acc[3].y += w * f.y;
            f = bf2f(u1.x); acc[4].x += w * f.x; acc[4].y += w * f.y;
            f = bf2f(u1.y); acc[5].x += w * f.x; acc[5].y += w * f.y;
            f = bf2f(u1.z); acc[6].x += w * f.x; acc[6].y += w * f.y;
            f = bf2f(u1.w); acc[7].x += w * f.x; acc[7].y += w * f.y;
            ed = edn;
        }
    }
    const float2* bb = (const float2*)b1;   // 256 float2
    uint32_t ow[8];
#pragma unroll
    for (int j = 0; j < 8; j++) {
        int wordIdx = (j < 4) ? (4 * lane + j) : (128 + 4 * lane + (j - 4));
        float2 bv = bb[wordIdx];
        float lo = fmaxf(dc * acc[j].x + bv.x, 0.f);
        float hi = fmaxf(dc * acc[j].y + bv.y, 0.f);
        ow[j] = pack_bf2(lo, hi);
    }
    uint4* out = (uint4*)g_a1b;
    out[(size_t)node * 64 + lane]      = make_uint4(ow[0], ow[1], ow[2], ow[3]);
    out[(size_t)node * 64 + lane + 32] = make_uint4(ow[4], ow[5], ow[6], ow[7]);
}

// ---------------- aggregation layer 2 (bf16 h2) fused with FC+sigmoid --------
__global__ __launch_bounds__(256)
void agg2_fc_kernel(const float* __restrict__ b2, const float* __restrict__ Wfc,
                    const float* __restrict__ bfc, float* __restrict__ out) {
    __shared__ float sh[8][128];
    __shared__ float sWfc[D2 * DOUT];
    for (int i = threadIdx.x; i < D2 * DOUT; i += blockDim.x) sWfc[i] = Wfc[i];
    __syncthreads();

    int wid = threadIdx.x >> 5;
    int lane = threadIdx.x & 31;
    int node = blockIdx.x * 8 + wid;

    if (node < N_NODES) {
        const uint2* h = (const uint2*)g_h2b;   // 32 uint2 per row
        float dc = g_dis[node];
        uint2 v = h[(size_t)node * 32 + lane];
        float2 f0 = bf2f(v.x), f1 = bf2f(v.y);
        float2 acc0 = make_float2(f0.x * dc, f0.y * dc);
        float2 acc1 = make_float2(f1.x * dc, f1.y * dc);
        int beg = g_rowptr[node], end = g_rowptr[node + 1];
        for (int e = beg; e < end; e++) {
            int2 ed = g_edge[e];
            int r = ed.x;
            float w = __int_as_float(ed.y);
            uint2 u = h[(size_t)r * 32 + lane];
            float2 g0 = bf2f(u.x), g1 = bf2f(u.y);
            acc0.x += w * g0.x; acc0.y += w * g0.y;
            acc1.x += w * g1.x; acc1.y += w * g1.y;
        }
        const float2* bb = (const float2*)b2;
        float2 b0 = bb[2 * lane], b1v = bb[2 * lane + 1];
        sh[wid][lane * 4 + 0] = fmaxf(dc * acc0.x + b0.x, 0.f);
        sh[wid][lane * 4 + 1] = fmaxf(dc * acc0.y + b0.y, 0.f);
        sh[wid][lane * 4 + 2] = fmaxf(dc * acc1.x + b1v.x, 0.f);
        sh[wid][lane * 4 + 3] = fmaxf(dc * acc1.y + b1v.y, 0.f);
    }
    __syncwarp();
    if (node < N_NODES && lane < DOUT) {
        float s = bfc[lane];
#pragma unroll 8
        for (int d = 0; d < D2; d++) s += sh[wid][d] * sWfc[d * DOUT + lane];
        out[(size_t)node * DOUT + lane] = 1.f / (1.f + expf(-s));
    }
}

// ---------------- launch ----------------
// Our launch #4 = edge_deg (profiled slot) this round.
extern "C" void kernel_launch(void* const* d_in, const int* in_sizes, int n_in,
                              void* d_out, int out_size) {
    const float* x   = (const float*)d_in[0];
    const void*  eix = d_in[1];
    const float* ew  = (const float*)d_in[2];
    const float* W1  = (const float*)d_in[3];
    const float* b1  = (const float*)d_in[4];
    const float* W2  = (const float*)d_in[5];
    const float* b2  = (const float*)d_in[6];
    const float* Wfc = (const float*)d_in[7];
    const float* bfc = (const float*)d_in[8];
    float* out = (float*)d_out;

    uint32_t *w1p, *w2p, *h1b, *a1b, *h2b;
    cudaGetSymbolAddress((void**)&w1p, g_w1p);
    cudaGetSymbolAddress((void**)&w2p, g_w2p);
    cudaGetSymbolAddress((void**)&h1b, g_h1b);
    cudaGetSymbolAddress((void**)&a1b, g_a1b);
    cudaGetSymbolAddress((void**)&h2b, g_h2b);

    cudaFuncSetAttribute(f32a_gemm, cudaFuncAttributeMaxDynamicSharedMemorySize,
                         GEMM1_SMEM_BYTES);
    cudaFuncSetAttribute(bf16gemm, cudaFuncAttributeMaxDynamicSharedMemorySize,
                         GEMM_SMEM_BYTES);

    const int TB = 256;
    detect_init_kernel<<<(N_NODES + TB - 1) / TB, TB>>>(eix);                  // 1
    conv_w_both<<<(W1_TOTAL + W2_TOTAL + TB - 1) / TB, TB>>>(W1, W2, w1p, w2p);// 2

    dim3 g1(D1 / BN, (N_NODES + BM - 1) / BM);
    f32a_gemm<<<g1, 256, GEMM1_SMEM_BYTES>>>(x, w1p, h1b, N_NODES, D0, D1);    // 3

    edge_deg_kernel<<<(N_EDGES + TB - 1) / TB, TB>>>(eix, ew);                 // 4 <- ncu
    scan_p1<<<SCAN_NB, SCAN_TB>>>();                                           // 5
    scan_p2<<<1, 128>>>();                                                     // 6
    scan_p3<<<SCAN_NB, SCAN_TB>>>();                                           // 7
    scatter_kernel<<<(N_EDGES + TB - 1) / TB, TB>>>(eix, ew);                  // 8

    agg1_kernel<<<(N_NODES + 7) / 8, 256>>>(b1);                               // 9

    dim3 g2(D2 / BN, (N_NODES + BM - 1) / BM);
    bf16gemm<<<g2, 256, GEMM_SMEM_BYTES>>>(a1b, w2p, h2b, N_NODES, D1, D2);    // 10

    agg2_fc_kernel<<<(N_NODES + 7) / 8, 256>>>(b2, Wfc, bfc, out);             // 11
}